// round 6
// baseline (speedup 1.0000x reference)
#include <cuda_runtime.h>
#include <cuda_bf16.h>
#include <stdint.h>

constexpr int B    = 4;
constexpr int H    = 8;
constexpr int LQ   = 1024;
constexpr int DH   = 64;
constexpr int KLEN = 1024;
constexpr int TBL  = 33;     // 2*MAX_REL_POS + 1
constexpr int QPAD = 68;     // staged row stride: 272B = 16B-aligned, bank-skewed

// Scratch: P[b][q][j][h]  (4*1024*33*8 floats = 4.3 MB)
__device__ float Pbuf[B * LQ * TBL * H];

__device__ __forceinline__ void ffma2(unsigned long long& acc,
                                      unsigned long long a,
                                      unsigned long long b)
{
    asm("fma.rn.f32x2 %0, %1, %2, %0;" : "+l"(acc) : "l"(a), "l"(b));
}
__device__ __forceinline__ float f2lo(unsigned long long v) {
    return __uint_as_float((unsigned)v);
}
__device__ __forceinline__ float f2hi(unsigned long long v) {
    return __uint_as_float((unsigned)(v >> 32));
}

// ---------------------------------------------------------------------------
// Kernel 1: P[b,q,j,h] = dot(query[b,h,q,:], table[j,:])
// One block = 32 consecutive rows (4 qpos x 8 h). Both q slab and table live
// in smem with 68-float row stride (conflict-free LDS.128 across 8 distinct
// rows). Thread (lr, oct): row lr, j in {oct, oct+8, ...}. Low regs,
// 1024 blocks -> full occupancy; FFMA2-packed math.
// ---------------------------------------------------------------------------
__global__ __launch_bounds__(256)
void proj_kernel(const float* __restrict__ q,
                 const float* __restrict__ table)
{
    __shared__ __align__(16) float qsh[32 * QPAD];
    __shared__ __align__(16) float tsh[TBL * QPAD];

    const int tid  = threadIdx.x;
    const int row0 = blockIdx.x * 32;      // first global row of this block

    // stage table: 33 x 64
    for (int i = tid; i < TBL * DH; i += 256) {
        int j = i >> 6, d = i & 63;
        tsh[j * QPAD + d] = table[i];
    }
    // stage q slab: 32 rows; row r -> (b, qpos, h)
    for (int i = tid; i < 32 * DH; i += 256) {
        int lr = i >> 6, d = i & 63;
        int r  = row0 + lr;
        int h  = r & 7;
        int qp = (r >> 3) & (LQ - 1);
        int b  = r >> 13;
        qsh[lr * QPAD + d] = q[(((size_t)b * H + h) * LQ + qp) * DH + d];
    }
    __syncthreads();

    const int lr  = tid >> 3;
    const int oct = tid & 7;
    const int r   = row0 + lr;
    float* pout = Pbuf + (size_t)(r >> 3) * (TBL * H) + (r & 7);

    const ulonglong2* qrow = reinterpret_cast<const ulonglong2*>(&qsh[lr * QPAD]);

    #pragma unroll
    for (int i = 0; i < 5; i++) {
        int j = oct + 8 * i;
        if (j < TBL) {
            const ulonglong2* trow =
                reinterpret_cast<const ulonglong2*>(&tsh[j * QPAD]);
            unsigned long long a0 = 0ull, a1 = 0ull;
            #pragma unroll
            for (int c = 0; c < 16; c++) {      // 16 x ull2 = 64 floats (FULL row)
                ulonglong2 qa = qrow[c];
                ulonglong2 ta = trow[c];
                ffma2(a0, qa.x, ta.x);
                ffma2(a1, qa.y, ta.y);
            }
            pout[j * H] = (f2lo(a0) + f2hi(a0)) + (f2lo(a1) + f2hi(a1));
        }
    }
}

// ---------------------------------------------------------------------------
// Kernel 2: out[b,h,q,k] = P[b,q, idx(b,q,k), h]
// One block per (b,q). idx from registers (int4 load of time_ids). P slab
// staged TRANSPOSED in smem as S2[h][34]; per-h gather = 4 scalar LDS
// (near-broadcast: time ids sorted) + 1 streaming STG.128. Low register
// count -> high occupancy to pipeline the stores.
// ---------------------------------------------------------------------------
__global__ __launch_bounds__(256)
void gather_kernel(const int* __restrict__ tids,
                   float* __restrict__ out)
{
    const int blk  = blockIdx.x;        // 0 .. B*LQ-1
    const int b    = blk >> 10;
    const int qpos = blk & (LQ - 1);
    const int tid  = threadIdx.x;

    __shared__ float S2[H * 34];        // [h][j], padded row stride 34

    for (int i = tid; i < TBL * H; i += 256) {
        // Pbuf layout: [j][h] -> transpose into [h][j]
        S2[(i & 7) * 34 + (i >> 3)] = Pbuf[(size_t)blk * (TBL * H) + i];
    }

    // idx for this thread's 4 k values, straight from registers
    const int tq = tids[b * KLEN + qpos];
    int4 t4 = reinterpret_cast<const int4*>(tids + (size_t)b * KLEN)[tid];

    int i0 = t4.x - tq; i0 = i0 < -16 ? -16 : (i0 > 16 ? 16 : i0); i0 += 16;
    int i1 = t4.y - tq; i1 = i1 < -16 ? -16 : (i1 > 16 ? 16 : i1); i1 += 16;
    int i2 = t4.z - tq; i2 = i2 < -16 ? -16 : (i2 > 16 ? 16 : i2); i2 += 16;
    int i3 = t4.w - tq; i3 = i3 < -16 ? -16 : (i3 > 16 ? 16 : i3); i3 += 16;

    __syncthreads();

    #pragma unroll
    for (int h = 0; h < H; h++) {
        const float* row = &S2[h * 34];
        float4 v;
        v.x = row[i0];
        v.y = row[i1];
        v.z = row[i2];
        v.w = row[i3];
        float4* o4 = reinterpret_cast<float4*>(
            out + ((((size_t)b * H + h) * LQ + qpos) * KLEN));
        __stcs(o4 + tid, v);
    }
}

extern "C" void kernel_launch(void* const* d_in, const int* in_sizes, int n_in,
                              void* d_out, int out_size)
{
    const float* q     = (const float*)d_in[0];
    const float* table = (const float*)d_in[1];
    const int*   tids  = (const int*)d_in[2];
    float*       out   = (float*)d_out;

    proj_kernel<<<(B * H * LQ) / 32, 256>>>(q, table);
    gather_kernel<<<B * LQ, 256>>>(tids, out);
}

// round 7
// speedup vs baseline: 1.0577x; 1.0577x over previous
#include <cuda_runtime.h>
#include <cuda_bf16.h>
#include <stdint.h>

constexpr int B    = 4;
constexpr int H    = 8;
constexpr int LQ   = 1024;
constexpr int DH   = 64;
constexpr int KLEN = 1024;
constexpr int TBL  = 33;     // 2*MAX_REL_POS + 1
constexpr int QPAD = 68;     // table row stride: 272B, 16B-aligned, bank-skewed
constexpr int SLAB = TBL * H; // 264 floats per (b,q)

// Scratch: P[b*q][j][h]  (4096 * 264 floats = 4.3 MB)
__device__ float Pbuf[B * LQ * SLAB];

__device__ __forceinline__ void ffma2(unsigned long long& acc,
                                      unsigned long long a,
                                      unsigned long long b)
{
    asm("fma.rn.f32x2 %0, %1, %2, %0;" : "+l"(acc) : "l"(a), "l"(b));
}
__device__ __forceinline__ float f2lo(unsigned long long v) {
    return __uint_as_float((unsigned)v);
}
__device__ __forceinline__ float f2hi(unsigned long long v) {
    return __uint_as_float((unsigned)(v >> 32));
}

// ---------------------------------------------------------------------------
// Kernel 1: P[bq, j, h] = dot(query[b,h,q,:], table[j,:])
// FOUR threads per row, split on j (j = jq, jq+4, ...). Each thread keeps the
// full 64-float q row in 16 ulonglong2 registers (loaded ONCE) and reads the
// table from smem. Within a warp each LDS.128 touches 4 distinct j-rows at
// 272B stride -> distinct bank quadrants -> 1 wavefront. Stores per j-step
// are a contiguous 128B warp write.
// ---------------------------------------------------------------------------
__global__ __launch_bounds__(256)
void proj_kernel(const float* __restrict__ q,
                 const float* __restrict__ table)
{
    __shared__ __align__(16) float tsh[TBL * QPAD];

    const int tid = threadIdx.x;

    // stage table: 33 x 64
    for (int i = tid; i < TBL * DH; i += 256) {
        tsh[(i >> 6) * QPAD + (i & 63)] = table[i];
    }

    const int gid = blockIdx.x * 256 + tid;   // 0 .. 131071
    const int jq  = gid & 3;                  // j-quarter
    const int row = gid >> 2;                 // 0 .. 32767
    const int h    = row & 7;
    const int qpos = (row >> 3) & (LQ - 1);
    const int b    = row >> 13;

    // q row -> registers (once)
    ulonglong2 qv[16];
    {
        const ulonglong2* qr = reinterpret_cast<const ulonglong2*>(
            q + (((size_t)b * H + h) * LQ + qpos) * DH);
        #pragma unroll
        for (int c = 0; c < 16; c++) qv[c] = qr[c];
    }
    __syncthreads();

    float* pout = Pbuf + (size_t)(row >> 3) * SLAB + h;

    #pragma unroll
    for (int i = 0; i < 9; i++) {
        int j = jq + 4 * i;
        if (j < TBL) {
            const ulonglong2* tr =
                reinterpret_cast<const ulonglong2*>(&tsh[j * QPAD]);
            unsigned long long a0 = 0ull, a1 = 0ull;
            #pragma unroll
            for (int c = 0; c < 16; c++) {
                ulonglong2 t = tr[c];
                ffma2(a0, qv[c].x, t.x);
                ffma2(a1, qv[c].y, t.y);
            }
            pout[j * H] = (f2lo(a0) + f2hi(a0)) + (f2lo(a1) + f2hi(a1));
        }
    }
}

// ---------------------------------------------------------------------------
// Kernel 2: out[b,h,q,k] = P[bq, idx(b,q,k), h]
// ONE WARP per (b,q): no block-wide barrier, 8 independent streams per block.
// Slab (264 floats) copied straight into this warp's smem strip (3 LDG.128
// per lane), then per k-chunk: idx from int4 time_ids in registers, gather
// S[idx*8+h] (broadcast-dominated: sorted ids => idx==0 or 32 for most k),
// streaming STG.128.
// ---------------------------------------------------------------------------
__global__ __launch_bounds__(256)
void gather_kernel(const int* __restrict__ tids,
                   float* __restrict__ out)
{
    __shared__ __align__(16) float S2[8][SLAB];   // one slab per warp

    const int tid  = threadIdx.x;
    const int w    = tid >> 5;
    const int lane = tid & 31;
    const int blk  = blockIdx.x * 8 + w;    // (b,q) index 0..4095
    const int b    = blk >> 10;
    const int qpos = blk & (LQ - 1);

    // stage slab: 264 floats = 66 float4 -> 3 vec loads for lanes 0..21
    {
        const float4* src = reinterpret_cast<const float4*>(
            Pbuf + (size_t)blk * SLAB);
        float4* dst = reinterpret_cast<float4*>(S2[w]);
        if (lane < 22) {
            dst[lane]      = src[lane];
            dst[lane + 22] = src[lane + 22];
            dst[lane + 44] = src[lane + 44];
        }
    }
    const int tq = tids[b * KLEN + qpos];
    __syncwarp();

    const int4* t4p = reinterpret_cast<const int4*>(tids + (size_t)b * KLEN);
    const float* S  = S2[w];

    #pragma unroll
    for (int c = 0; c < 8; c++) {
        int4 t4 = t4p[c * 32 + lane];
        int i0 = t4.x - tq; i0 = i0 < -16 ? -16 : (i0 > 16 ? 16 : i0); i0 += 16;
        int i1 = t4.y - tq; i1 = i1 < -16 ? -16 : (i1 > 16 ? 16 : i1); i1 += 16;
        int i2 = t4.z - tq; i2 = i2 < -16 ? -16 : (i2 > 16 ? 16 : i2); i2 += 16;
        int i3 = t4.w - tq; i3 = i3 < -16 ? -16 : (i3 > 16 ? 16 : i3); i3 += 16;

        #pragma unroll
        for (int h = 0; h < H; h++) {
            float4 v;
            v.x = S[i0 * 8 + h];
            v.y = S[i1 * 8 + h];
            v.z = S[i2 * 8 + h];
            v.w = S[i3 * 8 + h];
            float4* o4 = reinterpret_cast<float4*>(
                out + ((((size_t)b * H + h) * LQ + qpos) * KLEN) + c * 128);
            __stcs(o4 + lane, v);
        }
    }
}

extern "C" void kernel_launch(void* const* d_in, const int* in_sizes, int n_in,
                              void* d_out, int out_size)
{
    const float* q     = (const float*)d_in[0];
    const float* table = (const float*)d_in[1];
    const int*   tids  = (const int*)d_in[2];
    float*       out   = (float*)d_out;

    proj_kernel<<<(B * H * LQ * 4) / 256, 256>>>(q, table);
    gather_kernel<<<(B * LQ) / 8, 256>>>(tids, out);
}

// round 8
// speedup vs baseline: 1.1628x; 1.0994x over previous
#include <cuda_runtime.h>
#include <cuda_bf16.h>
#include <stdint.h>

constexpr int B    = 4;
constexpr int H    = 8;
constexpr int LQ   = 1024;
constexpr int DH   = 64;
constexpr int KLEN = 1024;
constexpr int TBL  = 33;      // 2*MAX_REL_POS + 1
constexpr int SLAB = TBL * H; // 264 floats per (b,q)

// Scratch: P[bq][j][h]  (4096 * 264 floats = 4.3 MB)
__device__ float Pbuf[B * LQ * SLAB];

__device__ __forceinline__ void ffma2(unsigned long long& acc,
                                      unsigned long long a,
                                      unsigned long long b)
{
    asm("fma.rn.f32x2 %0, %1, %2, %0;" : "+l"(acc) : "l"(a), "l"(b));
}
__device__ __forceinline__ float f2lo(unsigned long long v) {
    return __uint_as_float((unsigned)v);
}
__device__ __forceinline__ float f2hi(unsigned long long v) {
    return __uint_as_float((unsigned)(v >> 32));
}

// ---------------------------------------------------------------------------
// Kernel 1: P[row, j] = dot(qrow[row,:], table[j,:]),  row = (b,qpos,h)
// Register-tiled GEMM. Operands staged TRANSPOSED in smem:
//   qsh2[p][row]  (p = d-pair)  -> lane-consecutive rows = dense LDS.64
//   tsh2[p][j]                  -> warp-uniform j = broadcast LDS.64
// Warp w owns j in {3w, 3w+1, 3w+2} (11 warps x 3 = 33, exact).
// Lane l owns rows {l, l+32, l+64, l+96}. Thread tile = 4 rows x 3 j,
// accumulated in 12 packed f32x2 regs; 12 FFMA2 per 7 LDS.64.
// ---------------------------------------------------------------------------
__global__ __launch_bounds__(352)
void proj_kernel(const float* __restrict__ q,
                 const float* __restrict__ table)
{
    __shared__ __align__(16) float2 qsh2[32][128];  // [d-pair][row]   32 KB
    __shared__ __align__(16) float2 tsh2[32][34];   // [d-pair][j]    8.5 KB

    const int tid = threadIdx.x;
    const int R0  = blockIdx.x * 128;   // first global row of this block

    // stage q transposed: 128 rows x 32 pairs
    for (int i = tid; i < 128 * 32; i += 352) {
        int rl = i >> 5;                // local row
        int p  = i & 31;                // d-pair
        int r  = R0 + rl;
        int h    = r & 7;
        int qpos = (r >> 3) & (LQ - 1);
        int b    = r >> 13;
        qsh2[p][rl] = reinterpret_cast<const float2*>(
            q + (((size_t)b * H + h) * LQ + qpos) * DH)[p];
    }
    // stage table transposed: 33 rows x 32 pairs
    for (int i = tid; i < TBL * 32; i += 352) {
        int j = i >> 5;
        int p = i & 31;
        tsh2[p][j] = reinterpret_cast<const float2*>(table)[i];
    }
    __syncthreads();

    const int w  = tid >> 5;       // warp = j-triple (0..10)
    const int l  = tid & 31;       // lane = base row
    const int j0 = w * 3;

    unsigned long long acc[4][3];
    #pragma unroll
    for (int k = 0; k < 4; k++)
        #pragma unroll
        for (int m = 0; m < 3; m++) acc[k][m] = 0ull;

    #pragma unroll 4
    for (int p = 0; p < 32; p++) {
        const unsigned long long* qp =
            reinterpret_cast<const unsigned long long*>(&qsh2[p][0]);
        const unsigned long long* tp =
            reinterpret_cast<const unsigned long long*>(&tsh2[p][0]);
        unsigned long long qv0 = qp[l];
        unsigned long long qv1 = qp[l + 32];
        unsigned long long qv2 = qp[l + 64];
        unsigned long long qv3 = qp[l + 96];
        unsigned long long tv0 = tp[j0];
        unsigned long long tv1 = tp[j0 + 1];
        unsigned long long tv2 = tp[j0 + 2];
        ffma2(acc[0][0], qv0, tv0); ffma2(acc[0][1], qv0, tv1); ffma2(acc[0][2], qv0, tv2);
        ffma2(acc[1][0], qv1, tv0); ffma2(acc[1][1], qv1, tv1); ffma2(acc[1][2], qv1, tv2);
        ffma2(acc[2][0], qv2, tv0); ffma2(acc[2][1], qv2, tv1); ffma2(acc[2][2], qv2, tv2);
        ffma2(acc[3][0], qv3, tv0); ffma2(acc[3][1], qv3, tv1); ffma2(acc[3][2], qv3, tv2);
    }

    // epilogue: P[bq][j][h]
    #pragma unroll
    for (int k = 0; k < 4; k++) {
        int r  = R0 + l + 32 * k;
        float* base = Pbuf + (size_t)(r >> 3) * SLAB + (r & 7);
        #pragma unroll
        for (int m = 0; m < 3; m++) {
            base[(j0 + m) * H] = (f2lo(acc[k][m]) + f2hi(acc[k][m]));
        }
    }
}

// ---------------------------------------------------------------------------
// Kernel 2: out[b,h,q,k] = P[bq, idx(b,q,k), h]
// One block per (b,q). Gather into a 32 KB smem tile [h][1024 k], then push
// each contiguous 4 KB row out[b,h,qpos,:] with cp.async.bulk (TMA bulk
// store) -- global stores leave the SM issue path entirely.
// ---------------------------------------------------------------------------
__global__ __launch_bounds__(256)
void gather_kernel(const int* __restrict__ tids,
                   float* __restrict__ out)
{
    __shared__ __align__(16) float S[SLAB];           // 1 KB slab
    __shared__ __align__(16) float tile[H * KLEN];    // 32 KB out tile [h][k]

    const int blk  = blockIdx.x;        // (b,q) index
    const int b    = blk >> 10;
    const int qpos = blk & (LQ - 1);
    const int tid  = threadIdx.x;

    if (tid < 66) {
        reinterpret_cast<float4*>(S)[tid] =
            reinterpret_cast<const float4*>(Pbuf + (size_t)blk * SLAB)[tid];
    }

    const int tq = tids[b * KLEN + qpos];
    int4 t4 = reinterpret_cast<const int4*>(tids + (size_t)b * KLEN)[tid];
    int i0 = t4.x - tq; i0 = i0 < -16 ? -16 : (i0 > 16 ? 16 : i0); i0 += 16;
    int i1 = t4.y - tq; i1 = i1 < -16 ? -16 : (i1 > 16 ? 16 : i1); i1 += 16;
    int i2 = t4.z - tq; i2 = i2 < -16 ? -16 : (i2 > 16 ? 16 : i2); i2 += 16;
    int i3 = t4.w - tq; i3 = i3 < -16 ? -16 : (i3 > 16 ? 16 : i3); i3 += 16;

    __syncthreads();

    #pragma unroll
    for (int h = 0; h < H; h++) {
        float4 v;
        v.x = S[i0 * H + h];
        v.y = S[i1 * H + h];
        v.z = S[i2 * H + h];
        v.w = S[i3 * H + h];
        reinterpret_cast<float4*>(tile + h * KLEN)[tid] = v;
    }
    __syncthreads();

    if (tid == 0) {
        asm volatile("fence.proxy.async.shared::cta;" ::: "memory");
        #pragma unroll
        for (int h = 0; h < H; h++) {
            const float* gdst = out + (((size_t)b * H + h) * LQ + qpos) * KLEN;
            uint32_t ssrc;
            asm("{ .reg .u64 t; cvta.to.shared.u64 t, %1; cvt.u32.u64 %0, t; }"
                : "=r"(ssrc) : "l"(tile + h * KLEN));
            asm volatile(
                "cp.async.bulk.global.shared::cta.bulk_group [%0], [%1], %2;"
                :: "l"(gdst), "r"(ssrc), "r"(KLEN * 4) : "memory");
        }
        asm volatile("cp.async.bulk.commit_group;" ::: "memory");
        asm volatile("cp.async.bulk.wait_group 0;" ::: "memory");
    }
}

extern "C" void kernel_launch(void* const* d_in, const int* in_sizes, int n_in,
                              void* d_out, int out_size)
{
    const float* q     = (const float*)d_in[0];
    const float* table = (const float*)d_in[1];
    const int*   tids  = (const int*)d_in[2];
    float*       out   = (float*)d_out;

    proj_kernel<<<(B * H * LQ) / 128, 352>>>(q, table);
    gather_kernel<<<B * LQ, 256>>>(tids, out);
}

// round 9
// speedup vs baseline: 1.3369x; 1.1498x over previous
#include <cuda_runtime.h>
#include <cuda_bf16.h>
#include <stdint.h>

constexpr int B    = 4;
constexpr int H    = 8;
constexpr int LQ   = 1024;
constexpr int DH   = 64;
constexpr int KLEN = 1024;
constexpr int TBL  = 33;     // 2*MAX_REL_POS + 1
constexpr int TP   = 68;     // padded row stride (272B): conflict-free LDS.128
constexpr int PS   = 34;     // S2 row stride

__device__ __forceinline__ void ffma2(unsigned long long& acc,
                                      unsigned long long a,
                                      unsigned long long b)
{
    asm("fma.rn.f32x2 %0, %1, %2, %0;" : "+l"(acc) : "l"(a), "l"(b));
}
__device__ __forceinline__ float f2lo(unsigned long long v) {
    return __uint_as_float((unsigned)v);
}
__device__ __forceinline__ float f2hi(unsigned long long v) {
    return __uint_as_float((unsigned)(v >> 32));
}

// ---------------------------------------------------------------------------
// Fused kernel: one block per (b,q).
//   1) stage table (33x64, pad 68) + q slab (8x64, pad 68) in smem
//   2) S[h][j] = dot(q[b,h,qpos,:], table[j,:])
//        warp = h, lane = j; per 16B chunk: broadcast q LDS.128 (1 wf) +
//        conflict-free table LDS.128 (4 wf, 272B lane stride) + 2 FFMA2.
//        j=32 tail handled by 8 predicated threads of warp 0.
//   3) out[b,h,qpos,k] = S[h][idx(k)]; idx from int4 time_ids in registers;
//        8 coalesced streaming STG.128 per thread.
// S-compute (~700 smem wavefronts/block) hides under the output-store wall.
// ---------------------------------------------------------------------------
__global__ __launch_bounds__(256)
void relpe_fused(const float* __restrict__ q,
                 const float* __restrict__ table,
                 const int* __restrict__ tids,
                 float* __restrict__ out)
{
    __shared__ __align__(16) float tsh[TBL * TP];   // 8.8 KB
    __shared__ __align__(16) float qsh[H * TP];     // 2.1 KB
    __shared__ float S2[H * PS];                    // 1.1 KB

    const int blk  = blockIdx.x;        // (b,q) index
    const int b    = blk >> 10;
    const int qpos = blk & (LQ - 1);
    const int tid  = threadIdx.x;

    // ---- stage table: 2112 floats = 528 float4 ----
    {
        const float4* t4 = reinterpret_cast<const float4*>(table);
        for (int i = tid; i < (TBL * DH) / 4; i += 256) {
            float4 v = t4[i];
            int j  = i >> 4;          // 16 float4 per row
            int c4 = i & 15;
            *reinterpret_cast<float4*>(&tsh[j * TP + 4 * c4]) = v;
        }
    }
    // ---- stage q slab: 512 floats = 128 float4 ----
    if (tid < (H * DH) / 4) {
        int h  = tid >> 4;
        int c4 = tid & 15;
        float4 v = reinterpret_cast<const float4*>(
            q + (((size_t)b * H + h) * LQ + qpos) * DH)[c4];
        *reinterpret_cast<float4*>(&qsh[h * TP + 4 * c4]) = v;
    }

    // ---- idx for this thread's 4 k values (independent of staging) ----
    const int tq = tids[b * KLEN + qpos];
    int4 t4i = reinterpret_cast<const int4*>(tids + (size_t)b * KLEN)[tid];
    int i0 = t4i.x - tq; i0 = i0 < -16 ? -16 : (i0 > 16 ? 16 : i0); i0 += 16;
    int i1 = t4i.y - tq; i1 = i1 < -16 ? -16 : (i1 > 16 ? 16 : i1); i1 += 16;
    int i2 = t4i.z - tq; i2 = i2 < -16 ? -16 : (i2 > 16 ? 16 : i2); i2 += 16;
    int i3 = t4i.w - tq; i3 = i3 < -16 ? -16 : (i3 > 16 ? 16 : i3); i3 += 16;

    __syncthreads();

    // ---- S compute: warp = h, lane = j ----
    {
        const int h  = tid >> 5;
        const int jl = tid & 31;
        const ulonglong2* qrow =
            reinterpret_cast<const ulonglong2*>(&qsh[h * TP]);
        const ulonglong2* trow =
            reinterpret_cast<const ulonglong2*>(&tsh[jl * TP]);
        unsigned long long a0 = 0ull, a1 = 0ull;
        #pragma unroll
        for (int c = 0; c < 16; c++) {
            ulonglong2 qa = qrow[c];    // broadcast within warp
            ulonglong2 ta = trow[c];    // conflict-free (272B lane stride)
            ffma2(a0, qa.x, ta.x);
            ffma2(a1, qa.y, ta.y);
        }
        S2[h * PS + jl] = (f2lo(a0) + f2hi(a0)) + (f2lo(a1) + f2hi(a1));

        // tail: j = 32, computed by threads 0..7 (h = tid)
        if (tid < H) {
            const ulonglong2* qr2 =
                reinterpret_cast<const ulonglong2*>(&qsh[tid * TP]);
            const ulonglong2* tr2 =
                reinterpret_cast<const ulonglong2*>(&tsh[32 * TP]);
            unsigned long long b0 = 0ull, b1 = 0ull;
            #pragma unroll
            for (int c = 0; c < 16; c++) {
                ulonglong2 qa = qr2[c];
                ulonglong2 ta = tr2[c];
                ffma2(b0, qa.x, ta.x);
                ffma2(b1, qa.y, ta.y);
            }
            S2[tid * PS + 32] = (f2lo(b0) + f2hi(b0)) + (f2lo(b1) + f2hi(b1));
        }
    }
    __syncthreads();

    // ---- gather + stream: 8 coalesced float4 stores per thread ----
    #pragma unroll
    for (int h = 0; h < H; h++) {
        const float* row = &S2[h * PS];
        float4 v;
        v.x = row[i0];
        v.y = row[i1];
        v.z = row[i2];
        v.w = row[i3];
        float4* o4 = reinterpret_cast<float4*>(
            out + ((((size_t)b * H + h) * LQ + qpos) * KLEN));
        __stcs(o4 + tid, v);
    }
}

extern "C" void kernel_launch(void* const* d_in, const int* in_sizes, int n_in,
                              void* d_out, int out_size)
{
    const float* q     = (const float*)d_in[0];
    const float* table = (const float*)d_in[1];
    const int*   tids  = (const int*)d_in[2];
    float*       out   = (float*)d_out;

    relpe_fused<<<B * LQ, 256>>>(q, table, tids, out);
}